// round 1
// baseline (speedup 1.0000x reference)
#include <cuda_runtime.h>

// Word2Vec negative-sampling loss:
//   out[b,0]   = softplus(-dot(syn0[inputs[b]], syn1[labels[b]]))
//   out[b,1+n] = softplus( dot(syn0[inputs[b]], syn1[sampled[n,b]]))
// B=16384, H=128, N=5, V=1e6.
// One warp per batch element; each lane owns a float4 slice of the H=128 row.

#define H 128
#define NNEG 5

__global__ __launch_bounds__(256) void w2v_kernel(
    const int* __restrict__ inputs,
    const int* __restrict__ labels,
    const int* __restrict__ sampled,   // [N, B]
    const float* __restrict__ syn0,    // [V, H]
    const float* __restrict__ syn1,    // [V, H]
    float* __restrict__ out,           // [B, 1+N]
    int B)
{
    int warp = (blockIdx.x * blockDim.x + threadIdx.x) >> 5;
    int lane = threadIdx.x & 31;
    if (warp >= B) return;
    const int b = warp;

    // Gather indices (broadcast loads within the warp)
    int tgt[1 + NNEG];
    const int inp = __ldg(&inputs[b]);
    tgt[0] = __ldg(&labels[b]);
#pragma unroll
    for (int n = 0; n < NNEG; n++)
        tgt[1 + n] = __ldg(&sampled[n * B + b]);

    // Front-batch all 7 row loads: 1x syn0 row + 6x syn1 rows.
    // Each lane loads 16B -> one LDG.E.128 per row per lane, 512B/warp/row.
    const int hoff = lane * 4;
    float4 u = *reinterpret_cast<const float4*>(
        syn0 + (long long)inp * H + hoff);

    float4 v[1 + NNEG];
#pragma unroll
    for (int t = 0; t < 1 + NNEG; t++)
        v[t] = *reinterpret_cast<const float4*>(
            syn1 + (long long)tgt[t] * H + hoff);

    // 6 dot products + warp butterfly reductions
    float dot[1 + NNEG];
#pragma unroll
    for (int t = 0; t < 1 + NNEG; t++) {
        float d = u.x * v[t].x + u.y * v[t].y + u.z * v[t].z + u.w * v[t].w;
#pragma unroll
        for (int o = 16; o > 0; o >>= 1)
            d += __shfl_xor_sync(0xffffffffu, d, o);
        dot[t] = d;
    }

    if (lane == 0) {
        // stable softplus(x) = max(x,0) + log1p(exp(-|x|))
        // true logit: softplus(-x); negatives: softplus(x)
        float x0 = -dot[0];
        out[b * (1 + NNEG) + 0] = fmaxf(x0, 0.0f) + log1pf(__expf(-fabsf(x0)));
#pragma unroll
        for (int t = 1; t < 1 + NNEG; t++) {
            float x = dot[t];
            out[b * (1 + NNEG) + t] = fmaxf(x, 0.0f) + log1pf(__expf(-fabsf(x)));
        }
    }
}

extern "C" void kernel_launch(void* const* d_in, const int* in_sizes, int n_in,
                              void* d_out, int out_size)
{
    const int*   inputs  = (const int*)d_in[0];
    const int*   labels  = (const int*)d_in[1];
    const int*   sampled = (const int*)d_in[2];
    const float* syn0    = (const float*)d_in[3];
    const float* syn1    = (const float*)d_in[4];
    float*       out     = (float*)d_out;

    const int B = in_sizes[0];
    const int threads = 256;                 // 8 warps/block
    const int blocks  = (B * 32 + threads - 1) / threads;
    w2v_kernel<<<blocks, threads>>>(inputs, labels, sampled, syn0, syn1, out, B);
}